// round 4
// baseline (speedup 1.0000x reference)
#include <cuda_runtime.h>
#include <cuda_bf16.h>

#define NMAX 100000
#define EMAX 3200000

// ---------------- device scratch (no allocations allowed) ----------------
__device__ int   d_deg[NMAX];
__device__ int   d_ptr[NMAX + 1];
__device__ int   d_pos[NMAX];
__device__ int   d_csr[EMAX];
__device__ float d_dinv[NMAX];
__device__ float d_hs1[NMAX * 32];   // dinv-scaled X@W1
__device__ float d_a1 [NMAX * 32];   // relu(layer1)
__device__ float d_hs2[NMAX * 16];   // dinv-scaled a1@W2

// ---------------- graph preprocessing ----------------
__global__ void zero_deg_k(int n) {
    int i = blockIdx.x * blockDim.x + threadIdx.x;
    if (i < n) d_deg[i] = 0;
}

__global__ void count_k(const int* __restrict__ dst, int E, int n) {
    int i = blockIdx.x * blockDim.x + threadIdx.x;
    if (i < E) {
        int d = dst[i];
        if ((unsigned)d < (unsigned)n) atomicAdd(&d_deg[d], 1);
    }
}

// single-block exclusive scan + dinv computation + pos init
__global__ void scan_k(int n) {
    __shared__ int sums[1024];
    const int T = 1024;
    int tid = threadIdx.x;
    int chunk = (n + T - 1) / T;
    int beg = tid * chunk;
    int end = beg + chunk; if (end > n) end = n;
    int s = 0;
    for (int i = beg; i < end; i++) s += d_deg[i];
    sums[tid] = s;
    __syncthreads();
    // Kogge-Stone inclusive scan over 1024 partials
    for (int off = 1; off < T; off <<= 1) {
        int v = (tid >= off) ? sums[tid - off] : 0;
        __syncthreads();
        sums[tid] += v;
        __syncthreads();
    }
    int run = (tid == 0) ? 0 : sums[tid - 1];
    for (int i = beg; i < end; i++) {
        int d = d_deg[i];
        d_ptr[i] = run;
        d_pos[i] = run;
        d_dinv[i] = rsqrtf((float)(d + 1));   // +1 self loop; always > 0
        run += d;
    }
    if (tid == T - 1) d_ptr[n] = run;
}

__global__ void scatter_k(const int* __restrict__ src,
                          const int* __restrict__ dst, int E, int n) {
    int i = blockIdx.x * blockDim.x + threadIdx.x;
    if (i < E) {
        int d = dst[i];
        int s = src[i];
        if ((unsigned)d < (unsigned)n && (unsigned)s < (unsigned)n) {
            int p = atomicAdd(&d_pos[d], 1);
            d_csr[p] = s;
        }
    }
}

// ---------------- layer 1 matmul: hs1 = dinv * (X @ W1), 128 -> 32 ----------------
__global__ void mm1_k(const float* __restrict__ x, const float* __restrict__ W1, int n) {
    __shared__ float wt[32][132];   // transposed W1, padded; rows stay 16B-aligned (528B)
    int tid = threadIdx.x;
    for (int idx = tid; idx < 4096; idx += blockDim.x) {
        int k = idx >> 5, f = idx & 31;
        wt[f][k] = W1[idx];
    }
    __syncthreads();
    int warp = tid >> 5, lane = tid & 31;
    int node = blockIdx.x * (blockDim.x >> 5) + warp;
    if (node >= n) return;
    const float4* __restrict__ xr = reinterpret_cast<const float4*>(x + (size_t)node * 128);
    float acc = 0.f;
#pragma unroll
    for (int k4 = 0; k4 < 32; k4++) {
        float4 xv = xr[k4];                                       // broadcast within warp
        float4 wv = *reinterpret_cast<const float4*>(&wt[lane][k4 * 4]);
        acc += xv.x * wv.x + xv.y * wv.y + xv.z * wv.z + xv.w * wv.w;
    }
    d_hs1[node * 32 + lane] = acc * d_dinv[node];
}

// ---------------- layer 1 gather: a1 = relu(dinv*(self + sum_nbr hs1) + b1) ----------------
__global__ void gather1_k(const float* __restrict__ b1, int n) {
    int warp = (blockIdx.x * blockDim.x + threadIdx.x) >> 5;
    if (warp >= n) return;
    int lane = threadIdx.x & 31;
    float acc = d_hs1[warp * 32 + lane];          // self loop term (pre-scaled by dinv[self])
    int beg = d_ptr[warp], end = d_ptr[warp + 1];
    for (int e0 = beg; e0 < end; e0 += 32) {
        int r = end - e0;
        int s = (lane < r) ? d_csr[e0 + lane] : 0;
        int lim = r < 32 ? r : 32;
        for (int j = 0; j < lim; j++) {
            int sj = __shfl_sync(0xffffffffu, s, j);
            acc += d_hs1[sj * 32 + lane];         // coalesced 128B per neighbor
        }
    }
    d_a1[warp * 32 + lane] = fmaxf(d_dinv[warp] * acc + b1[lane], 0.f);
}

// ---------------- layer 2 matmul: hs2 = dinv * (a1 @ W2), 32 -> 16 ----------------
__global__ void mm2_k(const float* __restrict__ W2, int n) {
    __shared__ float w2s[512];
    int tid = threadIdx.x;
    for (int i = tid; i < 512; i += blockDim.x) w2s[i] = W2[i];   // FIX: full 512 staged
    __syncthreads();
    int id = blockIdx.x * blockDim.x + tid;
    if (id >= n * 16) return;
    int node = id >> 4, g = id & 15;
    const float* row = d_a1 + node * 32;
    float acc = 0.f;
#pragma unroll
    for (int k = 0; k < 32; k++) acc += row[k] * w2s[k * 16 + g];
    d_hs2[id] = acc * d_dinv[node];
}

// ---------------- layer 2 gather fused with final linear 16 -> 1 ----------------
__global__ void gather2_k(const float* __restrict__ b2, const float* __restrict__ Wl,
                          const float* __restrict__ bl, float* __restrict__ out, int n) {
    int warp = (blockIdx.x * blockDim.x + threadIdx.x) >> 5;
    if (warp >= n) return;
    int lane = threadIdx.x & 31;
    int f = lane & 15, g = lane >> 4;             // halves process alternating neighbors
    float acc = (g == 0) ? d_hs2[warp * 16 + f] : 0.f;   // self loop once
    int beg = d_ptr[warp], end = d_ptr[warp + 1];
    for (int e = beg + g; e < end; e += 2)
        acc += d_hs2[d_csr[e] * 16 + f];          // two coalesced 64B loads per warp step
    acc += __shfl_xor_sync(0xffffffffu, acc, 16);
    float v = fmaxf(d_dinv[warp] * acc + b2[f], 0.f) * Wl[f];
    v += __shfl_xor_sync(0xffffffffu, v, 8);
    v += __shfl_xor_sync(0xffffffffu, v, 4);
    v += __shfl_xor_sync(0xffffffffu, v, 2);
    v += __shfl_xor_sync(0xffffffffu, v, 1);
    if (lane == 0) out[warp] = v + bl[0];
}

// ---------------- launch ----------------
extern "C" void kernel_launch(void* const* d_in, const int* in_sizes, int n_in,
                              void* d_out, int out_size) {
    const float* x  = (const float*)d_in[0];
    const int*   ei = (const int*)d_in[1];      // edge_index materialized as int32
    const float* W1 = (const float*)d_in[2];
    const float* b1 = (const float*)d_in[3];
    const float* W2 = (const float*)d_in[4];
    const float* b2 = (const float*)d_in[5];
    const float* Wl = (const float*)d_in[6];
    const float* bl = (const float*)d_in[7];
    float* out = (float*)d_out;

    int n = in_sizes[0] / 128;
    int E = in_sizes[1] / 2;
    if (n > NMAX) n = NMAX;
    if (E > EMAX) E = EMAX;
    const int* src = ei;
    const int* dst = ei + E;

    zero_deg_k<<<(n + 255) / 256, 256>>>(n);
    count_k  <<<(E + 255) / 256, 256>>>(dst, E, n);
    scan_k   <<<1, 1024>>>(n);
    scatter_k<<<(E + 255) / 256, 256>>>(src, dst, E, n);

    mm1_k    <<<(n + 7) / 8, 256>>>(x, W1, n);
    gather1_k<<<(n + 7) / 8, 256>>>(b1, n);
    mm2_k    <<<(n * 16 + 255) / 256, 256>>>(W2, n);
    gather2_k<<<(n + 7) / 8, 256>>>(b2, Wl, bl, out, n);
}

// round 5
// speedup vs baseline: 1.8326x; 1.8326x over previous
#include <cuda_runtime.h>
#include <cuda_bf16.h>

#define NMAX 100000
#define EMAX 3200000
#define SCAN_T 512
#define SCAN_BMAX 256

// ---------------- device scratch (no allocations allowed) ----------------
__device__ int   d_deg[NMAX];
__device__ int   d_ptr[NMAX + 1];
__device__ int   d_pos[NMAX];
__device__ int   d_csr[EMAX];
__device__ float d_dinv[NMAX];
__device__ int   d_bsum[SCAN_BMAX];
__device__ int   d_boff[SCAN_BMAX];
__device__ float d_hs1[NMAX * 32];   // dinv-scaled X@W1
__device__ float d_a1 [NMAX * 32];   // relu(layer1)
__device__ float d_hs2[NMAX * 16];   // dinv-scaled a1@W2

// ---------------- graph preprocessing ----------------
__global__ void zero_deg_k(int n) {
    int i = blockIdx.x * blockDim.x + threadIdx.x;
    if (i < n) d_deg[i] = 0;
}

__global__ void count4_k(const int* __restrict__ dst, int E, int n) {
    int i = blockIdx.x * blockDim.x + threadIdx.x;
    int E4 = E >> 2;
    if (i < E4) {
        int4 v = reinterpret_cast<const int4*>(dst)[i];
        if ((unsigned)v.x < (unsigned)n) atomicAdd(&d_deg[v.x], 1);
        if ((unsigned)v.y < (unsigned)n) atomicAdd(&d_deg[v.y], 1);
        if ((unsigned)v.z < (unsigned)n) atomicAdd(&d_deg[v.z], 1);
        if ((unsigned)v.w < (unsigned)n) atomicAdd(&d_deg[v.w], 1);
    }
    if (i == 0) {                                  // tail (E % 4)
        for (int e = E4 << 2; e < E; e++) {
            int d = dst[e];
            if ((unsigned)d < (unsigned)n) atomicAdd(&d_deg[d], 1);
        }
    }
}

// --- 3-phase scan: per-block reduce -> scan partials -> per-block emit ---
__global__ void partial_k(int n) {
    __shared__ int red[SCAN_T];
    int t = threadIdx.x;
    int i = blockIdx.x * SCAN_T + t;
    red[t] = (i < n) ? d_deg[i] : 0;
    __syncthreads();
#pragma unroll
    for (int s = SCAN_T / 2; s > 0; s >>= 1) {
        if (t < s) red[t] += red[t + s];
        __syncthreads();
    }
    if (t == 0) d_bsum[blockIdx.x] = red[0];
}

__global__ void bscan_k(int nblk, int n) {
    __shared__ int sc[SCAN_BMAX];
    int t = threadIdx.x;
    int v = (t < nblk) ? d_bsum[t] : 0;
    sc[t] = v;
    __syncthreads();
#pragma unroll
    for (int off = 1; off < SCAN_BMAX; off <<= 1) {
        int u = (t >= off) ? sc[t - off] : 0;
        __syncthreads();
        sc[t] += u;
        __syncthreads();
    }
    if (t < nblk) d_boff[t] = sc[t] - v;           // exclusive block offsets
    if (t == SCAN_BMAX - 1) d_ptr[n] = sc[SCAN_BMAX - 1];
}

__global__ void emit_k(int n) {
    __shared__ int sc[SCAN_T];
    int t = threadIdx.x;
    int i = blockIdx.x * SCAN_T + t;
    int d = (i < n) ? d_deg[i] : 0;
    sc[t] = d;
    __syncthreads();
#pragma unroll
    for (int off = 1; off < SCAN_T; off <<= 1) {   // Kogge-Stone inclusive
        int u = (t >= off) ? sc[t - off] : 0;
        __syncthreads();
        sc[t] += u;
        __syncthreads();
    }
    if (i < n) {
        int excl = sc[t] - d + d_boff[blockIdx.x];
        d_ptr[i] = excl;
        d_pos[i] = excl;
        d_dinv[i] = rsqrtf((float)(d + 1));        // +1 self loop
    }
}

__global__ void scatter4_k(const int* __restrict__ src,
                           const int* __restrict__ dst, int E, int n) {
    int i = blockIdx.x * blockDim.x + threadIdx.x;
    int E4 = E >> 2;
    if (i < E4) {
        int4 s4 = reinterpret_cast<const int4*>(src)[i];
        int4 d4 = reinterpret_cast<const int4*>(dst)[i];
        if ((unsigned)d4.x < (unsigned)n && (unsigned)s4.x < (unsigned)n)
            d_csr[atomicAdd(&d_pos[d4.x], 1)] = s4.x;
        if ((unsigned)d4.y < (unsigned)n && (unsigned)s4.y < (unsigned)n)
            d_csr[atomicAdd(&d_pos[d4.y], 1)] = s4.y;
        if ((unsigned)d4.z < (unsigned)n && (unsigned)s4.z < (unsigned)n)
            d_csr[atomicAdd(&d_pos[d4.z], 1)] = s4.z;
        if ((unsigned)d4.w < (unsigned)n && (unsigned)s4.w < (unsigned)n)
            d_csr[atomicAdd(&d_pos[d4.w], 1)] = s4.w;
    }
    if (i == 0) {
        for (int e = E4 << 2; e < E; e++) {
            int d = dst[e], s = src[e];
            if ((unsigned)d < (unsigned)n && (unsigned)s < (unsigned)n)
                d_csr[atomicAdd(&d_pos[d], 1)] = s;
        }
    }
}

// ---------------- layer 1 matmul: hs1 = dinv * (X @ W1), 128 -> 32 ----------------
__global__ void mm1_k(const float* __restrict__ x, const float* __restrict__ W1, int n) {
    __shared__ float wt[32][132];   // transposed W1, padded; rows stay 16B-aligned (528B)
    int tid = threadIdx.x;
    for (int idx = tid; idx < 4096; idx += blockDim.x) {
        int k = idx >> 5, f = idx & 31;
        wt[f][k] = W1[idx];
    }
    __syncthreads();
    int warp = tid >> 5, lane = tid & 31;
    int node = blockIdx.x * (blockDim.x >> 5) + warp;
    if (node >= n) return;
    const float4* __restrict__ xr = reinterpret_cast<const float4*>(x + (size_t)node * 128);
    float acc = 0.f;
#pragma unroll
    for (int k4 = 0; k4 < 32; k4++) {
        float4 xv = xr[k4];                                       // broadcast within warp
        float4 wv = *reinterpret_cast<const float4*>(&wt[lane][k4 * 4]);
        acc += xv.x * wv.x + xv.y * wv.y + xv.z * wv.z + xv.w * wv.w;
    }
    d_hs1[node * 32 + lane] = acc * d_dinv[node];
}

// ---- layer 1 gather: 4 neighbor-groups x 8 float4-lanes; 4 full rows per warp-step ----
__global__ void gather1_k(const float* __restrict__ b1, int n) {
    int warp = (blockIdx.x * blockDim.x + threadIdx.x) >> 5;
    if (warp >= n) return;
    int lane = threadIdx.x & 31;
    int grp = lane >> 3, f4 = lane & 7;
    const float4* __restrict__ hs = reinterpret_cast<const float4*>(d_hs1);
    float4 acc = make_float4(0.f, 0.f, 0.f, 0.f);
    if (grp == 0) acc = hs[warp * 8 + f4];        // self loop (pre-scaled by dinv[self])
    int beg = d_ptr[warp], end = d_ptr[warp + 1];
    for (int e = beg + grp; e < end; e += 4) {
        int s = d_csr[e];                          // 4 distinct addrs/warp, sector-broadcast
        float4 v = hs[s * 8 + f4];                 // 512B per warp iteration
        acc.x += v.x; acc.y += v.y; acc.z += v.z; acc.w += v.w;
    }
#pragma unroll
    for (int off = 8; off < 32; off <<= 1) {       // combine the 4 groups
        acc.x += __shfl_xor_sync(0xffffffffu, acc.x, off);
        acc.y += __shfl_xor_sync(0xffffffffu, acc.y, off);
        acc.z += __shfl_xor_sync(0xffffffffu, acc.z, off);
        acc.w += __shfl_xor_sync(0xffffffffu, acc.w, off);
    }
    if (grp == 0) {
        float di = d_dinv[warp];
        float4 b = reinterpret_cast<const float4*>(b1)[f4];
        float4 r;
        r.x = fmaxf(di * acc.x + b.x, 0.f);
        r.y = fmaxf(di * acc.y + b.y, 0.f);
        r.z = fmaxf(di * acc.z + b.z, 0.f);
        r.w = fmaxf(di * acc.w + b.w, 0.f);
        reinterpret_cast<float4*>(d_a1)[warp * 8 + f4] = r;
    }
}

// ---------------- layer 2 matmul: hs2 = dinv * (a1 @ W2), 32 -> 16 ----------------
__global__ void mm2_k(const float* __restrict__ W2, int n) {
    __shared__ float w2s[512];
    int tid = threadIdx.x;
    for (int i = tid; i < 512; i += blockDim.x) w2s[i] = W2[i];
    __syncthreads();
    int id = blockIdx.x * blockDim.x + tid;
    if (id >= n * 16) return;
    int node = id >> 4, g = id & 15;
    const float* row = d_a1 + node * 32;
    float acc = 0.f;
#pragma unroll
    for (int k = 0; k < 32; k++) acc += row[k] * w2s[k * 16 + g];
    d_hs2[id] = acc * d_dinv[node];
}

// ---- layer 2 gather + final linear: 8 neighbor-groups x 4 float4-lanes ----
__global__ void gather2_k(const float* __restrict__ b2, const float* __restrict__ Wl,
                          const float* __restrict__ bl, float* __restrict__ out, int n) {
    int warp = (blockIdx.x * blockDim.x + threadIdx.x) >> 5;
    if (warp >= n) return;
    int lane = threadIdx.x & 31;
    int grp = lane >> 2, f4 = lane & 3;
    const float4* __restrict__ hs = reinterpret_cast<const float4*>(d_hs2);
    float4 acc = make_float4(0.f, 0.f, 0.f, 0.f);
    if (grp == 0) acc = hs[warp * 4 + f4];        // self loop once
    int beg = d_ptr[warp], end = d_ptr[warp + 1];
    for (int e = beg + grp; e < end; e += 8) {
        int s = d_csr[e];
        float4 v = hs[s * 4 + f4];                 // 512B per warp iteration (8 rows)
        acc.x += v.x; acc.y += v.y; acc.z += v.z; acc.w += v.w;
    }
#pragma unroll
    for (int off = 4; off < 32; off <<= 1) {       // combine the 8 groups
        acc.x += __shfl_xor_sync(0xffffffffu, acc.x, off);
        acc.y += __shfl_xor_sync(0xffffffffu, acc.y, off);
        acc.z += __shfl_xor_sync(0xffffffffu, acc.z, off);
        acc.w += __shfl_xor_sync(0xffffffffu, acc.w, off);
    }
    float v = 0.f;
    if (grp == 0) {
        float di = d_dinv[warp];
        float4 b  = reinterpret_cast<const float4*>(b2)[f4];
        float4 wl = reinterpret_cast<const float4*>(Wl)[f4];
        v  = fmaxf(di * acc.x + b.x, 0.f) * wl.x;
        v += fmaxf(di * acc.y + b.y, 0.f) * wl.y;
        v += fmaxf(di * acc.z + b.z, 0.f) * wl.z;
        v += fmaxf(di * acc.w + b.w, 0.f) * wl.w;
    }
    v += __shfl_xor_sync(0xffffffffu, v, 1);       // sum lanes 0..3
    v += __shfl_xor_sync(0xffffffffu, v, 2);
    if (lane == 0) out[warp] = v + bl[0];
}

// ---------------- launch ----------------
extern "C" void kernel_launch(void* const* d_in, const int* in_sizes, int n_in,
                              void* d_out, int out_size) {
    const float* x  = (const float*)d_in[0];
    const int*   ei = (const int*)d_in[1];      // edge_index materialized as int32
    const float* W1 = (const float*)d_in[2];
    const float* b1 = (const float*)d_in[3];
    const float* W2 = (const float*)d_in[4];
    const float* b2 = (const float*)d_in[5];
    const float* Wl = (const float*)d_in[6];
    const float* bl = (const float*)d_in[7];
    float* out = (float*)d_out;

    int n = in_sizes[0] / 128;
    int E = in_sizes[1] / 2;
    if (n > NMAX) n = NMAX;
    if (E > EMAX) E = EMAX;
    const int* src = ei;
    const int* dst = ei + E;
    int nblk = (n + SCAN_T - 1) / SCAN_T;       // <= 196 for NMAX

    zero_deg_k<<<(n + 255) / 256, 256>>>(n);
    count4_k  <<<((E >> 2) + 255) / 256, 256>>>(dst, E, n);
    partial_k <<<nblk, SCAN_T>>>(n);
    bscan_k   <<<1, SCAN_BMAX>>>(nblk, n);
    emit_k    <<<nblk, SCAN_T>>>(n);
    scatter4_k<<<((E >> 2) + 255) / 256, 256>>>(src, dst, E, n);

    mm1_k     <<<(n + 7) / 8, 256>>>(x, W1, n);
    gather1_k <<<(n + 7) / 8, 256>>>(b1, n);
    mm2_k     <<<(n * 16 + 255) / 256, 256>>>(W2, n);
    gather2_k <<<(n + 7) / 8, 256>>>(b2, Wl, bl, out, n);
}